// round 16
// baseline (speedup 1.0000x reference)
#include <cuda_runtime.h>
#include <cuda_fp16.h>
#include <math.h>
#include <stdint.h>

// Problem constants
#define Bb    2
#define Ss    2048
#define Kn    8
#define Dd    1024
#define DFFd  4096
#define NTOK  (Bb*Ss)        // 4096 tokens
#define MQKV  (NTOK*Kn)      // 32768 rows

// ----------------------------------------------------------------------------
// Scratch (static device globals; no runtime allocation)
// ----------------------------------------------------------------------------
__device__ __half g_sn_h[(size_t)MQKV * Dd];
__device__ __half g_U[(size_t)MQKV * Dd];
__device__ __half g_comb[(size_t)NTOK * Dd];
__device__ __half g_h[(size_t)NTOK * DFFd];
__device__ __half g_aggmix[(size_t)NTOK * Dd];
__device__ float  g_sfa[NTOK];
__device__ __half g_Wqt[(size_t)Dd * Dd];
__device__ __half g_Wkt[(size_t)Dd * Dd];
__device__ __half g_Mt[(size_t)Dd * Dd];
__device__ __half g_Wvh[(size_t)Dd * Dd];
__device__ __half g_Wuph[(size_t)DFFd * Dd];
__device__ __half g_Wdnh[(size_t)Dd * DFFd];
__device__ float  g_PV[32 * Dd];
__device__ float  g_vqk[Dd];
__device__ float  g_vkq[Dd];
__device__ float  g_pqbv[32];
__device__ float  g_c0[1];
__device__ float  g_zeros[Dd];

// ----------------------------------------------------------------------------
// Helpers (baseline ISA: cp.async / ldmatrix / mma.sync)
// ----------------------------------------------------------------------------
__device__ __forceinline__ uint32_t smem_u32(const void* p) {
    uint32_t a;
    asm("{ .reg .u64 t; cvta.to.shared.u64 t, %1; cvt.u32.u64 %0, t; }" : "=r"(a) : "l"(p));
    return a;
}
#define SW128(o) ((o) ^ (((o) >> 3) & 0x70))

__device__ __forceinline__ void cpa16(uint32_t s, const void* g) {
    asm volatile("cp.async.cg.shared.global [%0], [%1], 16;" :: "r"(s), "l"(g));
}
__device__ __forceinline__ void cpa_commit() {
    asm volatile("cp.async.commit_group;" ::: "memory");
}
template <int N>
__device__ __forceinline__ void cpa_wait() {
    asm volatile("cp.async.wait_group %0;" :: "n"(N) : "memory");
}
__device__ __forceinline__ void ldsm4(uint32_t& r0, uint32_t& r1, uint32_t& r2, uint32_t& r3,
                                      uint32_t addr) {
    asm volatile("ldmatrix.sync.aligned.m8n8.x4.shared.b16 {%0,%1,%2,%3}, [%4];"
                 : "=r"(r0), "=r"(r1), "=r"(r2), "=r"(r3) : "r"(addr));
}
// fp32-accumulator fp16 mma
__device__ __forceinline__ void mma_f16(float* c, uint32_t a0, uint32_t a1, uint32_t a2,
                                        uint32_t a3, uint32_t b0, uint32_t b1) {
    asm volatile(
        "mma.sync.aligned.m16n8k16.row.col.f32.f16.f16.f32 "
        "{%0,%1,%2,%3}, {%4,%5,%6,%7}, {%8,%9}, {%0,%1,%2,%3};"
        : "+f"(c[0]), "+f"(c[1]), "+f"(c[2]), "+f"(c[3])
        : "r"(a0), "r"(a1), "r"(a2), "r"(a3), "r"(b0), "r"(b1));
}
// fp16-accumulator mma, zero accumulator in
__device__ __forceinline__ void mma_f16h0(uint32_t& d0, uint32_t& d1,
                                          uint32_t a0, uint32_t a1, uint32_t a2, uint32_t a3,
                                          uint32_t b0, uint32_t b1) {
    asm volatile(
        "mma.sync.aligned.m16n8k16.row.col.f16.f16.f16.f16 "
        "{%0,%1}, {%2,%3,%4,%5}, {%6,%7}, {%8,%8};"
        : "=r"(d0), "=r"(d1)
        : "r"(a0), "r"(a1), "r"(a2), "r"(a3), "r"(b0), "r"(b1), "r"(0u));
}
// fp16-accumulator mma, in-place accumulate (d = a*b + d, all f16)
__device__ __forceinline__ void mma_f16hc(uint32_t& d0, uint32_t& d1,
                                          uint32_t a0, uint32_t a1, uint32_t a2, uint32_t a3,
                                          uint32_t b0, uint32_t b1) {
    asm volatile(
        "mma.sync.aligned.m16n8k16.row.col.f16.f16.f16.f16 "
        "{%0,%1}, {%2,%3,%4,%5}, {%6,%7}, {%0,%1};"
        : "+r"(d0), "+r"(d1)
        : "r"(a0), "r"(a1), "r"(a2), "r"(a3), "r"(b0), "r"(b1));
}
__device__ __forceinline__ void hacc_add(float* c, uint32_t d0, uint32_t d1) {
    float2 lo = __half22float2(*(__half2*)&d0);
    float2 hi = __half22float2(*(__half2*)&d1);
    c[0] += lo.x; c[1] += lo.y; c[2] += hi.x; c[3] += hi.y;
}
__device__ __forceinline__ float gelu_exact(float v) {
    return 0.5f * v * (1.0f + erff(v * 0.70710678118654752440f));
}

// ----------------------------------------------------------------------------
// Wide-tile U GEMM: C[M,1024] = A[M,1024] @ B[1024,1024]^T, all fp16.
// CTA 256x128, 8 warps as 4M x 2N (warp tile 64x64), BK=64, 2-stage cp.async.
// In-mma f16 accumulation: 32 independent fragment chains, distance-32 issue
// spacing, zero HADD2. Direct half2 stores. 2 CTAs/SM.
// ----------------------------------------------------------------------------
#define WSTG   49152
#define WB_OFF 32768

__global__ void __launch_bounds__(256, 2) gemm_wU(
    const __half* __restrict__ A,
    const __half* __restrict__ Bw,
    __half* __restrict__ C)
{
    extern __shared__ __align__(128) char dsm[];
    const uint32_t sbase = smem_u32(dsm);

    const int t    = threadIdx.x;
    const int warp = t >> 5;
    const int lane = t & 31;

    const int m0  = (blockIdx.x >> 3) * 256;
    const int n0  = (blockIdx.x & 7) * 128;
    const int wm0 = (warp >> 1) * 64;
    const int wn0 = (warp & 1) * 64;

    uint32_t hm[32][2];
    #pragma unroll
    for (int f = 0; f < 32; f++) { hm[f][0] = 0u; hm[f][1] = 0u; }

    const int NIT = Dd >> 6;   // 16

    auto load_stage = [&](int sl, int kIt) {
        const int k0 = kIt << 6;
        const uint32_t sb = sbase + sl * WSTG;
        #pragma unroll
        for (int i = 0; i < 8; i++) {
            int gi = t + 256 * i;
            int row = gi >> 3, g = gi & 7;
            cpa16(sb + SW128((uint32_t)(row * 128 + g * 16)),
                  A + (size_t)(m0 + row) * Dd + k0 + g * 8);
        }
        #pragma unroll
        for (int i = 0; i < 4; i++) {
            int gi = t + 256 * i;
            int row = gi >> 3, g = gi & 7;
            cpa16(sb + WB_OFF + SW128((uint32_t)(row * 128 + g * 16)),
                  Bw + (size_t)(n0 + row) * Dd + k0 + g * 8);
        }
        cpa_commit();
    };

    load_stage(0, 0);

    for (int it = 0; it < NIT; it++) {
        if (it + 1 < NIT) { load_stage((it + 1) & 1, it + 1); cpa_wait<1>(); }
        else              cpa_wait<0>();
        __syncthreads();

        const uint32_t ab = sbase + (it & 1) * WSTG;
        const uint32_t bb = ab + WB_OFF;

        #pragma unroll
        for (int s = 0; s < 4; s++) {
            uint32_t a[4][4];
            #pragma unroll
            for (int mf = 0; mf < 4; mf++) {
                int row = wm0 + mf * 16 + (lane & 15);
                uint32_t off = (uint32_t)(row * 128 + s * 32 + ((lane >> 4) << 4));
                ldsm4(a[mf][0], a[mf][1], a[mf][2], a[mf][3], ab + SW128(off));
            }
            #pragma unroll
            for (int cp = 0; cp < 4; cp++) {
                uint32_t b0, b1, b2, b3;
                int nrow = wn0 + cp * 16 + ((lane >> 4) << 3) + (lane & 7);
                uint32_t off = (uint32_t)(nrow * 128 + s * 32 + (((lane >> 3) & 1) << 4));
                ldsm4(b0, b1, b2, b3, bb + SW128(off));
                #pragma unroll
                for (int mf = 0; mf < 4; mf++) {
                    int f0 = mf * 8 + cp * 2 + 0, f1 = f0 + 1;
                    mma_f16hc(hm[f0][0], hm[f0][1],
                              a[mf][0], a[mf][1], a[mf][2], a[mf][3], b0, b1);
                    mma_f16hc(hm[f1][0], hm[f1][1],
                              a[mf][0], a[mf][1], a[mf][2], a[mf][3], b2, b3);
                }
            }
        }
        __syncthreads();
    }

    // Epilogue: direct half2 stores (no conversion)
    const int gid = lane >> 2, ctg = lane & 3;
    #pragma unroll
    for (int mf = 0; mf < 4; mf++) {
        int r0 = m0 + wm0 + mf * 16 + gid;
        #pragma unroll
        for (int nf = 0; nf < 8; nf++) {
            int f = mf * 8 + nf;
            int cc = n0 + wn0 + nf * 8 + ctg * 2;
            *(__half2*)(C + (size_t)r0 * Dd + cc)       = *(__half2*)&hm[f][0];
            *(__half2*)(C + (size_t)(r0 + 8) * Dd + cc) = *(__half2*)&hm[f][1];
        }
    }
}

// ----------------------------------------------------------------------------
// General fp16 GEMM: CTA 128x128, BK=64, 3-stage cp.async, SW128,
// 8 warps (4M x 2N), 2 CTAs/SM.
// MODE 0: f32 accumulation (exact)
// MODE 3: chain-2 f16 (back-to-back), spill f32 per 32 k-terms
// MODE 7: full f16 in-mma accumulation (distance-16 chains, zero HADD2)
// MODE 8: per-iteration (64-term) f16 in-mma chain + f32 spill per iteration
// act: 0 = +bias; 1 = +bias,gelu; 3 = +xadd + sfa[row]*bias.
// ----------------------------------------------------------------------------
#define STAGE_BYTES 32768
#define B_OFF       16384
#define DYN_SMEM    (3 * STAGE_BYTES)

template <int MODE>
__global__ void __launch_bounds__(256, 2) gemm_h(
    const __half* __restrict__ A, int lda,
    const __half* __restrict__ Bw,
    const float* __restrict__ bias,
    void* __restrict__ Cout, int ldc,
    int Kd, int Nt, int band_m, int act, int out_half,
    const float* __restrict__ xadd, const float* __restrict__ sfa)
{
    extern __shared__ __align__(128) char dsm[];
    const uint32_t sbase = smem_u32(dsm);

    const int t    = threadIdx.x;
    const int warp = t >> 5;
    const int lane = t & 31;

    const int tpb  = band_m * Nt;
    const int band = blockIdx.x / tpb;
    const int rem  = blockIdx.x % tpb;
    const int m0   = (band * band_m + rem % band_m) * 128;
    const int n0   = (rem / band_m) * 128;

    const int wm0 = (warp & 3) * 32;
    const int wn0 = (warp >> 2) * 64;

    float acc[(MODE == 7) ? 1 : 64];
    uint32_t hm[(MODE == 7) ? 16 : 1][2];
    if (MODE == 7) {
        #pragma unroll
        for (int f = 0; f < 16; f++) { hm[f][0] = 0u; hm[f][1] = 0u; }
    } else {
        #pragma unroll
        for (int i = 0; i < ((MODE == 7) ? 1 : 64); i++) acc[i] = 0.0f;
    }

    const int NIT = Kd >> 6;

    auto load_stage = [&](int sl, int kIt) {
        const int k0 = kIt << 6;
        const uint32_t sb = sbase + sl * STAGE_BYTES;
        #pragma unroll
        for (int i = 0; i < 4; i++) {
            int gi = t + 256 * i;
            int row = gi >> 3, g = gi & 7;
            cpa16(sb + SW128((uint32_t)(row * 128 + g * 16)),
                  A + (size_t)(m0 + row) * lda + k0 + g * 8);
        }
        #pragma unroll
        for (int i = 0; i < 4; i++) {
            int gi = t + 256 * i;
            int row = gi >> 3, g = gi & 7;
            cpa16(sb + B_OFF + SW128((uint32_t)(row * 128 + g * 16)),
                  Bw + (size_t)(n0 + row) * Kd + k0 + g * 8);
        }
        cpa_commit();
    };

    load_stage(0, 0);
    load_stage(1, 1);

    for (int it = 0; it < NIT; it++) {
        if (it + 2 < NIT) load_stage((it + 2) % 3, it + 2);
        if (it + 2 < NIT)      cpa_wait<2>();
        else if (it + 1 < NIT) cpa_wait<1>();
        else                   cpa_wait<0>();
        __syncthreads();

        const uint32_t ab = sbase + (it % 3) * STAGE_BYTES;
        const uint32_t bb = ab + B_OFF;

        if (MODE == 7) {
            #pragma unroll
            for (int s = 0; s < 4; s++) {
                uint32_t a[2][4];
                #pragma unroll
                for (int mf = 0; mf < 2; mf++) {
                    int row = wm0 + mf * 16 + (lane & 15);
                    uint32_t off = (uint32_t)(row * 128 + s * 32 + ((lane >> 4) << 4));
                    ldsm4(a[mf][0], a[mf][1], a[mf][2], a[mf][3], ab + SW128(off));
                }
                #pragma unroll
                for (int cp = 0; cp < 4; cp++) {
                    uint32_t b0, b1, b2, b3;
                    int nrow = wn0 + cp * 16 + ((lane >> 4) << 3) + (lane & 7);
                    uint32_t off = (uint32_t)(nrow * 128 + s * 32 + (((lane >> 3) & 1) << 4));
                    ldsm4(b0, b1, b2, b3, bb + SW128(off));
                    #pragma unroll
                    for (int mf = 0; mf < 2; mf++) {
                        int f0 = mf * 8 + cp * 2 + 0, f1 = f0 + 1;
                        mma_f16hc(hm[f0][0], hm[f0][1],
                                  a[mf][0], a[mf][1], a[mf][2], a[mf][3], b0, b1);
                        mma_f16hc(hm[f1][0], hm[f1][1],
                                  a[mf][0], a[mf][1], a[mf][2], a[mf][3], b2, b3);
                    }
                }
            }
        } else if (MODE == 8) {
            uint32_t hc[16][2];
            #pragma unroll
            for (int f = 0; f < 16; f++) { hc[f][0] = 0u; hc[f][1] = 0u; }
            #pragma unroll
            for (int s = 0; s < 4; s++) {
                uint32_t a[2][4];
                #pragma unroll
                for (int mf = 0; mf < 2; mf++) {
                    int row = wm0 + mf * 16 + (lane & 15);
                    uint32_t off = (uint32_t)(row * 128 + s * 32 + ((lane >> 4) << 4));
                    ldsm4(a[mf][0], a[mf][1], a[mf][2], a[mf][3], ab + SW128(off));
                }
                #pragma unroll
                for (int cp = 0; cp < 4; cp++) {
                    uint32_t b0, b1, b2, b3;
                    int nrow = wn0 + cp * 16 + ((lane >> 4) << 3) + (lane & 7);
                    uint32_t off = (uint32_t)(nrow * 128 + s * 32 + (((lane >> 3) & 1) << 4));
                    ldsm4(b0, b1, b2, b3, bb + SW128(off));
                    #pragma unroll
                    for (int mf = 0; mf < 2; mf++) {
                        int f0 = mf * 8 + cp * 2 + 0, f1 = f0 + 1;
                        mma_f16hc(hc[f0][0], hc[f0][1],
                                  a[mf][0], a[mf][1], a[mf][2], a[mf][3], b0, b1);
                        mma_f16hc(hc[f1][0], hc[f1][1],
                                  a[mf][0], a[mf][1], a[mf][2], a[mf][3], b2, b3);
                    }
                }
            }
            #pragma unroll
            for (int f = 0; f < 16; f++)
                hacc_add(&acc[f * 4], hc[f][0], hc[f][1]);
        } else if (MODE == 3) {
            #pragma unroll
            for (int sh = 0; sh < 2; sh++) {
                uint32_t a[2][2][4];
                #pragma unroll
                for (int ss = 0; ss < 2; ss++) {
                    const int s = sh * 2 + ss;
                    #pragma unroll
                    for (int mf = 0; mf < 2; mf++) {
                        int row = wm0 + mf * 16 + (lane & 15);
                        uint32_t off = (uint32_t)(row * 128 + s * 32 + ((lane >> 4) << 4));
                        ldsm4(a[ss][mf][0], a[ss][mf][1], a[ss][mf][2], a[ss][mf][3],
                              ab + SW128(off));
                    }
                }
                #pragma unroll
                for (int cp = 0; cp < 4; cp++) {
                    uint32_t b[2][4];
                    #pragma unroll
                    for (int ss = 0; ss < 2; ss++) {
                        const int s = sh * 2 + ss;
                        int nrow = wn0 + cp * 16 + ((lane >> 4) << 3) + (lane & 7);
                        uint32_t off = (uint32_t)(nrow * 128 + s * 32 + (((lane >> 3) & 1) << 4));
                        ldsm4(b[ss][0], b[ss][1], b[ss][2], b[ss][3], bb + SW128(off));
                    }
                    #pragma unroll
                    for (int mf = 0; mf < 2; mf++) {
                        #pragma unroll
                        for (int nh = 0; nh < 2; nh++) {
                            uint32_t d0, d1;
                            mma_f16h0(d0, d1, a[0][mf][0], a[0][mf][1], a[0][mf][2], a[0][mf][3],
                                      b[0][nh * 2], b[0][nh * 2 + 1]);
                            mma_f16hc(d0, d1, a[1][mf][0], a[1][mf][1], a[1][mf][2], a[1][mf][3],
                                      b[1][nh * 2], b[1][nh * 2 + 1]);
                            hacc_add(&acc[(mf * 8 + cp * 2 + nh) * 4], d0, d1);
                        }
                    }
                }
            }
        } else {
            #pragma unroll
            for (int s = 0; s < 4; s++) {
                uint32_t a[2][4];
                #pragma unroll
                for (int mf = 0; mf < 2; mf++) {
                    int row = wm0 + mf * 16 + (lane & 15);
                    uint32_t off = (uint32_t)(row * 128 + s * 32 + ((lane >> 4) << 4));
                    ldsm4(a[mf][0], a[mf][1], a[mf][2], a[mf][3], ab + SW128(off));
                }
                #pragma unroll
                for (int cp = 0; cp < 4; cp++) {
                    uint32_t b0, b1, b2, b3;
                    int nrow = wn0 + cp * 16 + ((lane >> 4) << 3) + (lane & 7);
                    uint32_t off = (uint32_t)(nrow * 128 + s * 32 + (((lane >> 3) & 1) << 4));
                    ldsm4(b0, b1, b2, b3, bb + SW128(off));
                    #pragma unroll
                    for (int mf = 0; mf < 2; mf++) {
                        mma_f16(&acc[(mf * 8 + cp * 2 + 0) * 4],
                                a[mf][0], a[mf][1], a[mf][2], a[mf][3], b0, b1);
                        mma_f16(&acc[(mf * 8 + cp * 2 + 1) * 4],
                                a[mf][0], a[mf][1], a[mf][2], a[mf][3], b2, b3);
                    }
                }
            }
        }
        __syncthreads();
    }

    // Epilogue (MODE7 unpacks hm per-fragment)
    const int gid = lane >> 2, ctg = lane & 3;
    float*  Cf = (float*)Cout;
    __half* Ch = (__half*)Cout;
    #pragma unroll
    for (int mf = 0; mf < 2; mf++) {
        int r0 = m0 + wm0 + mf * 16 + gid;
        float s0 = 0.0f, s1 = 0.0f;
        if (act == 3) { s0 = sfa[r0]; s1 = sfa[r0 + 8]; }
        #pragma unroll
        for (int nf = 0; nf < 8; nf++) {
            float c[4];
            if (MODE == 7) {
                int f = mf * 8 + nf;
                float2 lo = __half22float2(*(__half2*)&hm[f][0]);
                float2 hi = __half22float2(*(__half2*)&hm[f][1]);
                c[0] = lo.x; c[1] = lo.y; c[2] = hi.x; c[3] = hi.y;
            } else {
                c[0] = acc[(mf * 8 + nf) * 4 + 0];
                c[1] = acc[(mf * 8 + nf) * 4 + 1];
                c[2] = acc[(mf * 8 + nf) * 4 + 2];
                c[3] = acc[(mf * 8 + nf) * 4 + 3];
            }
            int cc = n0 + wn0 + nf * 8 + ctg * 2;
            float2 bv2 = *(const float2*)(bias + cc);
            float v0 = c[0], v1 = c[1], v2 = c[2], v3 = c[3];
            if (act == 3) {
                float2 x0 = *(const float2*)(xadd + (size_t)r0 * ldc + cc);
                float2 x1 = *(const float2*)(xadd + (size_t)(r0 + 8) * ldc + cc);
                v0 += x0.x + s0 * bv2.x; v1 += x0.y + s0 * bv2.y;
                v2 += x1.x + s1 * bv2.x; v3 += x1.y + s1 * bv2.y;
            } else {
                v0 += bv2.x; v1 += bv2.y; v2 += bv2.x; v3 += bv2.y;
                if (act == 1) {
                    v0 = gelu_exact(v0); v1 = gelu_exact(v1);
                    v2 = gelu_exact(v2); v3 = gelu_exact(v3);
                }
            }
            if (out_half) {
                *(__half2*)(Ch + (size_t)r0 * ldc + cc)       = __floats2half2_rn(v0, v1);
                *(__half2*)(Ch + (size_t)(r0 + 8) * ldc + cc) = __floats2half2_rn(v2, v3);
            } else {
                float2 o0 = {v0, v1}, o1 = {v2, v3};
                *(float2*)(Cf + (size_t)r0 * ldc + cc) = o0;
                *(float2*)(Cf + (size_t)(r0 + 8) * ldc + cc) = o1;
            }
        }
    }
}

// ----------------------------------------------------------------------------
// Merged prepass: transposes, weight f2h, bias precomputes — one launch.
// ----------------------------------------------------------------------------
__global__ void prep_all(
    __half* __restrict__ Wqt, const float* __restrict__ Wq,
    __half* __restrict__ Wkt, const float* __restrict__ Wk,
    __half* __restrict__ Wvh, const float* __restrict__ Wv,
    __half* __restrict__ Wuph, const float* __restrict__ Wup,
    __half* __restrict__ Wdnh, const float* __restrict__ Wdown,
    float* __restrict__ vqk, float* __restrict__ vkq,
    const float* __restrict__ bq, const float* __restrict__ bk,
    float* __restrict__ pqbv, float* __restrict__ c0,
    const float* __restrict__ pq, const float* __restrict__ bv,
    float* __restrict__ PV)
{
    __shared__ float tile[32][33];
    const int b   = blockIdx.x;
    const int tx  = threadIdx.x, ty = threadIdx.y;
    const int tid = ty * 32 + tx;

    if (b < 2048) {
        int z = b >> 10, r = b & 1023;
        const float* src = z ? Wk : Wq;
        __half* dst = z ? Wkt : Wqt;
        int bx = (r & 31) * 32, by = (r >> 5) * 32;
        #pragma unroll
        for (int rr = 0; rr < 32; rr += 8)
            tile[ty + rr][tx] = src[(size_t)(by + ty + rr) * Dd + bx + tx];
        __syncthreads();
        #pragma unroll
        for (int rr = 0; rr < 32; rr += 8)
            dst[(size_t)(bx + ty + rr) * Dd + by + tx] = __float2half_rn(tile[tx][ty + rr]);
    } else if (b < 3072) {
        int i = (b - 2048) * 256 + tid;
        float4 v = ((const float4*)Wv)[i];
        ((__half2*)Wvh)[2 * i]     = __floats2half2_rn(v.x, v.y);
        ((__half2*)Wvh)[2 * i + 1] = __floats2half2_rn(v.z, v.w);
    } else if (b < 7168) {
        int i = (b - 3072) * 256 + tid;
        float4 v = ((const float4*)Wup)[i];
        ((__half2*)Wuph)[2 * i]     = __floats2half2_rn(v.x, v.y);
        ((__half2*)Wuph)[2 * i + 1] = __floats2half2_rn(v.z, v.w);
    } else if (b < 11264) {
        int i = (b - 7168) * 256 + tid;
        float4 v = ((const float4*)Wdown)[i];
        ((__half2*)Wdnh)[2 * i]     = __floats2half2_rn(v.x, v.y);
        ((__half2*)Wdnh)[2 * i + 1] = __floats2half2_rn(v.z, v.w);
    } else if (b < 11272) {
        int idx = (b - 11264) * 256 + tid;
        if (idx < Dd) {
            float a = 0.0f;
            for (int e = 0; e < Dd; e++) a = fmaf(Wq[(size_t)e * Dd + idx], bk[e], a);
            vqk[idx] = a;
        } else {
            int d = idx - Dd;
            float a = 0.0f;
            for (int e = 0; e < Dd; e++) a = fmaf(Wk[(size_t)e * Dd + d], bq[e], a);
            vkq[d] = a;
        }
    } else if (b < 11305) {
        __shared__ float red[256];
        int bb = b - 11272;
        float a = 0.0f;
        if (bb < 32) {
            for (int e = tid; e < Dd; e += 256) a = fmaf(pq[(size_t)bb * Dd + e], bv[e], a);
        } else {
            for (int e = tid; e < Dd; e += 256) a = fmaf(bq[e], bk[e], a);
        }
        red[tid] = a; __syncthreads();
        for (int o = 128; o > 0; o >>= 1) { if (tid < o) red[tid] += red[tid + o]; __syncthreads(); }
        if (tid == 0) { if (bb < 32) pqbv[bb] = red[0]; else c0[0] = red[0]; }
    } else {
        int idx = b - 11305;
        int p = idx >> 2;
        int d = (idx & 3) * 256 + tid;
        float a = 0.0f;
        for (int e = 0; e < Dd; e++) a = fmaf(pq[(size_t)p * Dd + e], Wv[(size_t)e * Dd + d], a);
        PV[(size_t)p * Dd + d] = a;
    }
}

__global__ void f2h_k(__half* __restrict__ d, const float* __restrict__ s, int n4) {
    int i = blockIdx.x * blockDim.x + threadIdx.x;
    if (i < n4) {
        float4 v = ((const float4*)s)[i];
        ((__half2*)d)[2 * i]     = __floats2half2_rn(v.x, v.y);
        ((__half2*)d)[2 * i + 1] = __floats2half2_rn(v.z, v.w);
    }
}

// ----------------------------------------------------------------------------
// Fused per-token attention (factored). Reads U + sn (fp16); emits agg_mix(fp16)+sfa.
// ----------------------------------------------------------------------------
#define ATTN_SMEM ((8 * 1028 * 2 + 1028 + 1024) * 4)

__global__ __launch_bounds__(256, 2) void attn_fused(
    const __half* __restrict__ U, const __half* __restrict__ sn,
    const float* __restrict__ pq, const float* __restrict__ PV,
    const float* __restrict__ ctx, const float* __restrict__ tw,
    const float* __restrict__ vqk, const float* __restrict__ vkq,
    const float* __restrict__ pqbv, const float* __restrict__ c0p,
    __half* __restrict__ aggmix, float* __restrict__ sfaout)
{
    extern __shared__ float dynsm[];
    float* sSn   = dynsm;
    float* sMix  = sSn + 8 * 1028;
    float* sWMix = sMix + 8 * 1028;
    float* sCtx  = sWMix + 1028;

    __shared__ float sA[8][8];
    __shared__ float sW[8], sTq[8], sTk[8];
    __shared__ float sNB[32], sCB[32];
    __shared__ float sSel[4][8];
    __shared__ float sTw[4];
    __shared__ int   sTi[4];
    __shared__ float sFA[8];
    __shared__ float sC0;

    const int tok  = blockIdx.x;
    const int t    = threadIdx.x;
    const int warp = t >> 5;
    const int lane = t & 31;
    const float scale = 0.03125f;

    const __half* snt = sn + (size_t)tok * 8 * 1024;
    const __half* Ut  = U + (size_t)tok * 8 * 1024;

    if (t < 8) sW[t] = tw[tok * 8 + t];
    if (t == 0) sC0 = c0p[0];
    #pragma unroll
    for (int r = 0; r < 16; r++) {
        int i2 = t + 256 * r;
        __half2 v = ((const __half2*)snt)[i2];
        int d = i2 * 2;
        float* row = sSn + (d >> 10) * 1028 + (d & 1023);
        row[0] = __half2float(v.x); row[1] = __half2float(v.y);
    }
    #pragma unroll
    for (int r = 0; r < 4; r++) sCtx[t + 256 * r] = ctx[(size_t)tok * 1024 + t + 256 * r];
    __syncthreads();

    // ---- Stage 1 ----
    float sc[8] = {0, 0, 0, 0, 0, 0, 0, 0};
    {
        const int i = warp;
        const __half2* Urow = (const __half2*)(Ut + i * 1024);
        float tq = 0.0f, tk = 0.0f;
        for (int c = 0; c < 4; c++) {
            float2 uc[4];
            #pragma unroll
            for (int u = 0; u < 4; u++)
                uc[u] = __half22float2(Urow[c * 128 + u * 32 + lane]);
            #pragma unroll
            for (int j = 0; j < 8; j++) {
                const float* sj = sSn + j * 1028 + c * 256;
                float a = 0.0f;
                #pragma unroll
                for (int u = 0; u < 4; u++) {
                    float2 sv = *(const float2*)(sj + u * 64 + 2 * lane);
                    a = fmaf(uc[u].x, sv.x, a);
                    a = fmaf(uc[u].y, sv.y, a);
                }
                sc[j] += a;
            }
            const float* si = sSn + i * 1028 + c * 256;
            #pragma unroll
            for (int u = 0; u < 4; u++) {
                float2 sv = *(const float2*)(si + u * 64 + 2 * lane);
                float2 vq = *(const float2*)(vqk + c * 256 + u * 64 + 2 * lane);
                float2 vk = *(const float2*)(vkq + c * 256 + u * 64 + 2 * lane);
                tq = fmaf(sv.x, vq.x, tq); tq = fmaf(sv.y, vq.y, tq);
                tk = fmaf(sv.x, vk.x, tk); tk = fmaf(sv.y, vk.y, tk);
            }
        }
        #pragma unroll
        for (int j = 0; j < 8; j++) {
            float a = sc[j];
            #pragma unroll
            for (int o = 16; o > 0; o >>= 1) a += __shfl_xor_sync(0xffffffffu, a, o);
            sc[j] = a;
        }
        #pragma unroll
        for (int o = 16; o > 0; o >>= 1) {
            tq += __shfl_xor_sync(0xffffffffu, tq, o);
            tk += __shfl_xor_sync(0xffffffffu, tk, o);
        }
        if (lane == 0) { sTq[i] = tq; sTk[i] = tk; }
    }
    __syncthreads();
    {
        const int i = warp;
        float tqi = sTq[i], c0v = sC0;
        float f[8];
        #pragma unroll
        for (int j = 0; j < 8; j++) f[j] = (sc[j] + tqi + sTk[j] + c0v) * scale;
        if (lane == 0) {
            float m = f[0];
            #pragma unroll
            for (int j = 1; j < 8; j++) m = fmaxf(m, f[j]);
            float e[8], s = 0.0f;
            #pragma unroll
            for (int j = 0; j < 8; j++) { e[j] = expf(f[j] - m); s += e[j]; }
            float inv = 1.0f / s;
            #pragma unroll
            for (int j = 0; j < 8; j++) sA[i][j] = e[j] * inv;
        }
    }
    __syncthreads();

    // ---- Stage 2 ----
    #pragma unroll
    for (int r = 0; r < 4; r++) {
        int d = t + 256 * r;
        float a[8] = {0,0,0,0,0,0,0,0};
        #pragma unroll
        for (int j = 0; j < 8; j++) {
            float s = sSn[j * 1028 + d];
            #pragma unroll
            for (int i = 0; i < 8; i++) a[i] = fmaf(sA[i][j], s, a[i]);
        }
        float wm = 0.0f;
        #pragma unroll
        for (int i = 0; i < 8; i++) { sMix[i * 1028 + d] = a[i]; wm = fmaf(sW[i], a[i], wm); }
        sWMix[d] = wm;
    }
    __syncthreads();

    // ---- Stage 3 ----
    float swsum = sW[0] + sW[1] + sW[2] + sW[3] + sW[4] + sW[5] + sW[6] + sW[7];
    #pragma unroll
    for (int q = 0; q < 4; q++) {
        int p = warp * 4 + q;
        const float* PVp = PV + (size_t)p * 1024;
        const float* pqp = pq + (size_t)p * 1024;
        float nb = 0.0f, cb = 0.0f;
        #pragma unroll
        for (int u = 0; u < 32; u++) {
            int d = u * 32 + lane;
            nb = fmaf(PVp[d], sWMix[d], nb);
            cb = fmaf(pqp[d], sCtx[d], cb);
        }
        #pragma unroll
        for (int o = 16; o > 0; o >>= 1) {
            nb += __shfl_xor_sync(0xffffffffu, nb, o);
            cb += __shfl_xor_sync(0xffffffffu, cb, o);
        }
        if (lane == 0) { sNB[p] = (nb + swsum * pqbv[p]) * scale; sCB[p] = cb; }
    }
    __syncthreads();

    // ---- Stage 4 ----
    if (warp == 0) {
        float s = 0.5f * sNB[lane] + 0.5f * sCB[lane];
        float vals[4]; int ids[4];
        #pragma unroll
        for (int r = 0; r < 4; r++) {
            float v = s; int idx = lane;
            #pragma unroll
            for (int o = 16; o > 0; o >>= 1) {
                float ov = __shfl_xor_sync(0xffffffffu, v, o);
                int   oi = __shfl_xor_sync(0xffffffffu, idx, o);
                if (ov > v || (ov == v && oi < idx)) { v = ov; idx = oi; }
            }
            vals[r] = v; ids[r] = idx;
            if (lane == idx) s = -3.4e38f;
        }
        if (lane == 0) {
            float m = fmaxf(fmaxf(vals[0], vals[1]), fmaxf(vals[2], vals[3]));
            float e0 = expf(vals[0] - m), e1 = expf(vals[1] - m);
            float e2 = expf(vals[2] - m), e3 = expf(vals[3] - m);
            float inv = 1.0f / (e0 + e1 + e2 + e3);
            sTw[0] = e0 * inv; sTw[1] = e1 * inv; sTw[2] = e2 * inv; sTw[3] = e3 * inv;
            sTi[0] = ids[0]; sTi[1] = ids[1]; sTi[2] = ids[2]; sTi[3] = ids[3];
        }
    }
    __syncthreads();

    // ---- Stage 5 ----
    if (warp < 4) {
        int pi = sTi[warp];
        const float* PVp = PV + (size_t)pi * 1024;
        float pvr[32];
        #pragma unroll
        for (int u = 0; u < 32; u++) pvr[u] = PVp[u * 32 + lane];
        float sel[8];
        #pragma unroll
        for (int k = 0; k < 8; k++) {
            float a = 0.0f;
            #pragma unroll
            for (int u = 0; u < 32; u++)
                a = fmaf(pvr[u], sMix[k * 1028 + u * 32 + lane], a);
            #pragma unroll
            for (int o = 16; o > 0; o >>= 1) a += __shfl_xor_sync(0xffffffffu, a, o);
            sel[k] = a;
        }
        if (lane == 0) {
            float pb = pqbv[pi];
            #pragma unroll
            for (int k = 0; k < 8; k++) sel[k] = (sel[k] + pb) * scale;
            float m = sel[0];
            #pragma unroll
            for (int k = 1; k < 8; k++) m = fmaxf(m, sel[k]);
            float e[8], sum = 0.0f;
            #pragma unroll
            for (int k = 0; k < 8; k++) { e[k] = expf(sel[k] - m); sum += e[k]; }
            float f = sTw[warp] / sum;
            #pragma unroll
            for (int k = 0; k < 8; k++) sSel[warp][k] = e[k] * f;
        }
    }
    __syncthreads();
    if (t < 8) sFA[t] = sSel[0][t] + sSel[1][t] + sSel[2][t] + sSel[3][t];
    __syncthreads();

    // ---- Stage 6 ----
    float fa[8];
    #pragma unroll
    for (int k = 0; k < 8; k++) fa[k] = sFA[k];
    if (t == 0)
        sfaout[tok] = fa[0] + fa[1] + fa[2] + fa[3] + fa[4] + fa[5] + fa[6] + fa[7];
    #pragma unroll
    for (int r = 0; r < 4; r++) {
        int d = t + 256 * r;
        float a = 0.0f;
        #pragma unroll
        for (int k = 0; k < 8; k++) a = fmaf(fa[k], sMix[k * 1028 + d], a);
        aggmix[(size_t)tok * 1024 + d] = __float2half_rn(a);
    }
}

// ----------------------------------------------------------------------------
// Launch (U GEMM is launch #4 = ncu profile target)
// ----------------------------------------------------------------------------
extern "C" void kernel_launch(void* const* d_in, const int* in_sizes, int n_in,
                              void* d_out, int out_size)
{
    const float* x     = (const float*)d_in[0];
    const float* tw    = (const float*)d_in[3];
    const float* sn    = (const float*)d_in[4];
    const float* ctx   = (const float*)d_in[5];
    const float* Wq    = (const float*)d_in[6];
    const float* bq    = (const float*)d_in[7];
    const float* Wk    = (const float*)d_in[8];
    const float* bk    = (const float*)d_in[9];
    const float* Wv    = (const float*)d_in[10];
    const float* bv    = (const float*)d_in[11];
    const float* pq    = (const float*)d_in[12];
    const float* Wup   = (const float*)d_in[13];
    const float* bup   = (const float*)d_in[14];
    const float* Wdown = (const float*)d_in[15];
    const float* bdown = (const float*)d_in[16];
    float* out = (float*)d_out;

    __half *snh, *Up, *comb, *h, *aggmix, *Wqt, *Wkt, *Mt, *Wvh, *Wuph, *Wdnh;
    float *sfa, *PV, *vqk, *vkq, *pqbv, *c0, *zeros;
    cudaGetSymbolAddress((void**)&snh,    g_sn_h);
    cudaGetSymbolAddress((void**)&Up,     g_U);
    cudaGetSymbolAddress((void**)&comb,   g_comb);
    cudaGetSymbolAddress((void**)&h,      g_h);
    cudaGetSymbolAddress((void**)&aggmix, g_aggmix);
    cudaGetSymbolAddress((void**)&sfa,    g_sfa);
    cudaGetSymbolAddress((void**)&Wqt,    g_Wqt);
    cudaGetSymbolAddress((void**)&Wkt,    g_Wkt);
    cudaGetSymbolAddress((void**)&Mt,     g_Mt);
    cudaGetSymbolAddress((void**)&Wvh,    g_Wvh);
    cudaGetSymbolAddress((void**)&Wuph,   g_Wuph);
    cudaGetSymbolAddress((void**)&Wdnh,   g_Wdnh);
    cudaGetSymbolAddress((void**)&PV,     g_PV);
    cudaGetSymbolAddress((void**)&vqk,    g_vqk);
    cudaGetSymbolAddress((void**)&vkq,    g_vkq);
    cudaGetSymbolAddress((void**)&pqbv,   g_pqbv);
    cudaGetSymbolAddress((void**)&c0,     g_c0);
    cudaGetSymbolAddress((void**)&zeros,  g_zeros);

    cudaFuncSetAttribute((const void*)gemm_h<0>, cudaFuncAttributeMaxDynamicSharedMemorySize, DYN_SMEM);
    cudaFuncSetAttribute((const void*)gemm_h<3>, cudaFuncAttributeMaxDynamicSharedMemorySize, DYN_SMEM);
    cudaFuncSetAttribute((const void*)gemm_h<7>, cudaFuncAttributeMaxDynamicSharedMemorySize, DYN_SMEM);
    cudaFuncSetAttribute((const void*)gemm_h<8>, cudaFuncAttributeMaxDynamicSharedMemorySize, DYN_SMEM);
    cudaFuncSetAttribute((const void*)gemm_wU, cudaFuncAttributeMaxDynamicSharedMemorySize, 2 * WSTG);
    cudaFuncSetAttribute(attn_fused, cudaFuncAttributeMaxDynamicSharedMemorySize, ATTN_SMEM);

    // #1: merged prepass (transposes + weight f2h + bias precomputes)
    prep_all<<<11433, dim3(32, 8)>>>(Wqt, Wq, Wkt, Wk, Wvh, Wv, Wuph, Wup,
                                     Wdnh, Wdown, vqk, vkq, bq, bk,
                                     pqbv, c0, pq, bv, PV);
    // #2: sn -> fp16
    int n4 = (MQKV * Dd) / 4;
    f2h_k<<<(n4 + 255) / 256, 256>>>(snh, sn, n4);
    // #3: Mt = Wkt @ Wqt^T (f32 accum, small)
    gemm_h<0><<<64, 256, DYN_SMEM>>>(Wkt, Dd, Wqt, zeros, Mt, Dd,
                                     Dd, 8, 8, 0, 1, nullptr, nullptr);
    // #4: U = sn_h @ Mt^T -> fp16  [wide tile + in-mma f16 accumulation] (PROFILE)
    gemm_wU<<<(MQKV / 256) * 8, 256, 2 * WSTG>>>(snh, Mt, Up);

    // fused attention -> agg_mix (fp16), sfa
    attn_fused<<<NTOK, 256, ATTN_SMEM>>>(Up, snh, pq, PV, ctx, tw,
                                         vqk, vkq, pqbv, c0, aggmix, sfa);

    // comb = x + agg_mix @ Wv^T + sfa*bv  [MODE7]
    gemm_h<7><<<256, 256, DYN_SMEM>>>(aggmix, Dd, Wvh, bv, comb, Dd,
                                      Dd, 8, 16, 3, 1, x, sfa);

    // FFN up (+GELU)  [MODE8: 64-term f16 in-mma chain + f32 spill /iter]
    gemm_h<8><<<1024, 256, DYN_SMEM>>>(comb, Dd, Wuph, bup, h, DFFd,
                                       Dd, 32, 8, 1, 1, nullptr, nullptr);

    // FFN down -> fp32 output  [MODE3: chain-2, f32 spill /32]
    gemm_h<3><<<256, 256, DYN_SMEM>>>(h, DFFd, Wdnh, bdown, out, Dd,
                                      DFFd, 8, 16, 0, 0, nullptr, nullptr);
}

// round 17
// speedup vs baseline: 1.0099x; 1.0099x over previous
#include <cuda_runtime.h>
#include <cuda_fp16.h>
#include <math.h>
#include <stdint.h>

// Problem constants
#define Bb    2
#define Ss    2048
#define Kn    8
#define Dd    1024
#define DFFd  4096
#define NTOK  (Bb*Ss)        // 4096 tokens
#define MQKV  (NTOK*Kn)      // 32768 rows

// ----------------------------------------------------------------------------
// Scratch (static device globals; no runtime allocation)
// ----------------------------------------------------------------------------
__device__ __half g_sn_h[(size_t)MQKV * Dd];
__device__ __half g_U[(size_t)MQKV * Dd];
__device__ __half g_comb[(size_t)NTOK * Dd];
__device__ __half g_h[(size_t)NTOK * DFFd];
__device__ __half g_aggmix[(size_t)NTOK * Dd];
__device__ float  g_sfa[NTOK];
__device__ __half g_Wqt[(size_t)Dd * Dd];
__device__ __half g_Wkt[(size_t)Dd * Dd];
__device__ __half g_Mt[(size_t)Dd * Dd];
__device__ __half g_Wvh[(size_t)Dd * Dd];
__device__ __half g_Wuph[(size_t)DFFd * Dd];
__device__ __half g_Wdnh[(size_t)Dd * DFFd];
__device__ float  g_PV[32 * Dd];
__device__ float  g_vqk[Dd];
__device__ float  g_vkq[Dd];
__device__ float  g_pqbv[32];
__device__ float  g_c0[1];
__device__ float  g_zeros[Dd];

// ----------------------------------------------------------------------------
// Helpers (baseline ISA: cp.async / ldmatrix / mma.sync)
// ----------------------------------------------------------------------------
__device__ __forceinline__ uint32_t smem_u32(const void* p) {
    uint32_t a;
    asm("{ .reg .u64 t; cvta.to.shared.u64 t, %1; cvt.u32.u64 %0, t; }" : "=r"(a) : "l"(p));
    return a;
}
#define SW128(o) ((o) ^ (((o) >> 3) & 0x70))

__device__ __forceinline__ void cpa16(uint32_t s, const void* g) {
    asm volatile("cp.async.cg.shared.global [%0], [%1], 16;" :: "r"(s), "l"(g));
}
__device__ __forceinline__ void cpa_commit() {
    asm volatile("cp.async.commit_group;" ::: "memory");
}
template <int N>
__device__ __forceinline__ void cpa_wait() {
    asm volatile("cp.async.wait_group %0;" :: "n"(N) : "memory");
}
__device__ __forceinline__ void ldsm4(uint32_t& r0, uint32_t& r1, uint32_t& r2, uint32_t& r3,
                                      uint32_t addr) {
    asm volatile("ldmatrix.sync.aligned.m8n8.x4.shared.b16 {%0,%1,%2,%3}, [%4];"
                 : "=r"(r0), "=r"(r1), "=r"(r2), "=r"(r3) : "r"(addr));
}
// fp32-accumulator fp16 mma
__device__ __forceinline__ void mma_f16(float* c, uint32_t a0, uint32_t a1, uint32_t a2,
                                        uint32_t a3, uint32_t b0, uint32_t b1) {
    asm volatile(
        "mma.sync.aligned.m16n8k16.row.col.f32.f16.f16.f32 "
        "{%0,%1,%2,%3}, {%4,%5,%6,%7}, {%8,%9}, {%0,%1,%2,%3};"
        : "+f"(c[0]), "+f"(c[1]), "+f"(c[2]), "+f"(c[3])
        : "r"(a0), "r"(a1), "r"(a2), "r"(a3), "r"(b0), "r"(b1));
}
// fp16-accumulator mma, zero accumulator in
__device__ __forceinline__ void mma_f16h0(uint32_t& d0, uint32_t& d1,
                                          uint32_t a0, uint32_t a1, uint32_t a2, uint32_t a3,
                                          uint32_t b0, uint32_t b1) {
    asm volatile(
        "mma.sync.aligned.m16n8k16.row.col.f16.f16.f16.f16 "
        "{%0,%1}, {%2,%3,%4,%5}, {%6,%7}, {%8,%8};"
        : "=r"(d0), "=r"(d1)
        : "r"(a0), "r"(a1), "r"(a2), "r"(a3), "r"(b0), "r"(b1), "r"(0u));
}
// fp16-accumulator mma, in-place accumulate (d = a*b + d, all f16)
__device__ __forceinline__ void mma_f16hc(uint32_t& d0, uint32_t& d1,
                                          uint32_t a0, uint32_t a1, uint32_t a2, uint32_t a3,
                                          uint32_t b0, uint32_t b1) {
    asm volatile(
        "mma.sync.aligned.m16n8k16.row.col.f16.f16.f16.f16 "
        "{%0,%1}, {%2,%3,%4,%5}, {%6,%7}, {%0,%1};"
        : "+r"(d0), "+r"(d1)
        : "r"(a0), "r"(a1), "r"(a2), "r"(a3), "r"(b0), "r"(b1));
}
__device__ __forceinline__ void hacc_add(float* c, uint32_t d0, uint32_t d1) {
    float2 lo = __half22float2(*(__half2*)&d0);
    float2 hi = __half22float2(*(__half2*)&d1);
    c[0] += lo.x; c[1] += lo.y; c[2] += hi.x; c[3] += hi.y;
}
__device__ __forceinline__ float gelu_exact(float v) {
    return 0.5f * v * (1.0f + erff(v * 0.70710678118654752440f));
}

// ----------------------------------------------------------------------------
// General fp16 GEMM: CTA 128x128, BK=64, 3-stage cp.async, SW128,
// 8 warps (4M x 2N), 2 CTAs/SM. SINGLE barrier per k-iteration:
// prefetch issued AFTER the top-of-iteration barrier, so the same barrier
// protects stage reuse (readers finished before arriving at it).
// MODE 0: f32 accumulation (exact)
// MODE 3: chain-2 f16 (back-to-back), spill f32 per 32 k-terms
// MODE 7: full f16 in-mma accumulation (distance-16 chains, zero HADD2)
// MODE 8: per-iteration (64-term) f16 in-mma chain + f32 spill per iteration
// act: 0 = +bias; 1 = +bias,gelu; 3 = +xadd + sfa[row]*bias.
// ----------------------------------------------------------------------------
#define STAGE_BYTES 32768
#define B_OFF       16384
#define DYN_SMEM    (3 * STAGE_BYTES)

template <int MODE>
__global__ void __launch_bounds__(256, 2) gemm_h(
    const __half* __restrict__ A, int lda,
    const __half* __restrict__ Bw,
    const float* __restrict__ bias,
    void* __restrict__ Cout, int ldc,
    int Kd, int Nt, int band_m, int act, int out_half,
    const float* __restrict__ xadd, const float* __restrict__ sfa)
{
    extern __shared__ __align__(128) char dsm[];
    const uint32_t sbase = smem_u32(dsm);

    const int t    = threadIdx.x;
    const int warp = t >> 5;
    const int lane = t & 31;

    const int tpb  = band_m * Nt;
    const int band = blockIdx.x / tpb;
    const int rem  = blockIdx.x % tpb;
    const int m0   = (band * band_m + rem % band_m) * 128;
    const int n0   = (rem / band_m) * 128;

    const int wm0 = (warp & 3) * 32;
    const int wn0 = (warp >> 2) * 64;

    float acc[(MODE == 7) ? 1 : 64];
    uint32_t hm[(MODE == 7) ? 16 : 1][2];
    if (MODE == 7) {
        #pragma unroll
        for (int f = 0; f < 16; f++) { hm[f][0] = 0u; hm[f][1] = 0u; }
    } else {
        #pragma unroll
        for (int i = 0; i < ((MODE == 7) ? 1 : 64); i++) acc[i] = 0.0f;
    }

    const int NIT = Kd >> 6;

    auto load_stage = [&](int sl, int kIt) {
        const int k0 = kIt << 6;
        const uint32_t sb = sbase + sl * STAGE_BYTES;
        #pragma unroll
        for (int i = 0; i < 4; i++) {
            int gi = t + 256 * i;
            int row = gi >> 3, g = gi & 7;
            cpa16(sb + SW128((uint32_t)(row * 128 + g * 16)),
                  A + (size_t)(m0 + row) * lda + k0 + g * 8);
        }
        #pragma unroll
        for (int i = 0; i < 4; i++) {
            int gi = t + 256 * i;
            int row = gi >> 3, g = gi & 7;
            cpa16(sb + B_OFF + SW128((uint32_t)(row * 128 + g * 16)),
                  Bw + (size_t)(n0 + row) * Kd + k0 + g * 8);
        }
        cpa_commit();
    };

    // Prologue: groups 0 and 1 in flight.
    load_stage(0, 0);
    load_stage(1, 1);

    for (int it = 0; it < NIT; it++) {
        // Wait for group `it` (one group may remain pending).
        if (it + 1 < NIT) cpa_wait<1>();
        else              cpa_wait<0>();
        __syncthreads();                      // data visible AND stage (it+2)%3 free
        if (it + 2 < NIT) load_stage((it + 2) % 3, it + 2);

        const uint32_t ab = sbase + (it % 3) * STAGE_BYTES;
        const uint32_t bb = ab + B_OFF;

        if (MODE == 7) {
            #pragma unroll
            for (int s = 0; s < 4; s++) {
                uint32_t a[2][4];
                #pragma unroll
                for (int mf = 0; mf < 2; mf++) {
                    int row = wm0 + mf * 16 + (lane & 15);
                    uint32_t off = (uint32_t)(row * 128 + s * 32 + ((lane >> 4) << 4));
                    ldsm4(a[mf][0], a[mf][1], a[mf][2], a[mf][3], ab + SW128(off));
                }
                #pragma unroll
                for (int cp = 0; cp < 4; cp++) {
                    uint32_t b0, b1, b2, b3;
                    int nrow = wn0 + cp * 16 + ((lane >> 4) << 3) + (lane & 7);
                    uint32_t off = (uint32_t)(nrow * 128 + s * 32 + (((lane >> 3) & 1) << 4));
                    ldsm4(b0, b1, b2, b3, bb + SW128(off));
                    #pragma unroll
                    for (int mf = 0; mf < 2; mf++) {
                        int f0 = mf * 8 + cp * 2 + 0, f1 = f0 + 1;
                        mma_f16hc(hm[f0][0], hm[f0][1],
                                  a[mf][0], a[mf][1], a[mf][2], a[mf][3], b0, b1);
                        mma_f16hc(hm[f1][0], hm[f1][1],
                                  a[mf][0], a[mf][1], a[mf][2], a[mf][3], b2, b3);
                    }
                }
            }
        } else if (MODE == 8) {
            uint32_t hc[16][2];
            #pragma unroll
            for (int f = 0; f < 16; f++) { hc[f][0] = 0u; hc[f][1] = 0u; }
            #pragma unroll
            for (int s = 0; s < 4; s++) {
                uint32_t a[2][4];
                #pragma unroll
                for (int mf = 0; mf < 2; mf++) {
                    int row = wm0 + mf * 16 + (lane & 15);
                    uint32_t off = (uint32_t)(row * 128 + s * 32 + ((lane >> 4) << 4));
                    ldsm4(a[mf][0], a[mf][1], a[mf][2], a[mf][3], ab + SW128(off));
                }
                #pragma unroll
                for (int cp = 0; cp < 4; cp++) {
                    uint32_t b0, b1, b2, b3;
                    int nrow = wn0 + cp * 16 + ((lane >> 4) << 3) + (lane & 7);
                    uint32_t off = (uint32_t)(nrow * 128 + s * 32 + (((lane >> 3) & 1) << 4));
                    ldsm4(b0, b1, b2, b3, bb + SW128(off));
                    #pragma unroll
                    for (int mf = 0; mf < 2; mf++) {
                        int f0 = mf * 8 + cp * 2 + 0, f1 = f0 + 1;
                        mma_f16hc(hc[f0][0], hc[f0][1],
                                  a[mf][0], a[mf][1], a[mf][2], a[mf][3], b0, b1);
                        mma_f16hc(hc[f1][0], hc[f1][1],
                                  a[mf][0], a[mf][1], a[mf][2], a[mf][3], b2, b3);
                    }
                }
            }
            #pragma unroll
            for (int f = 0; f < 16; f++)
                hacc_add(&acc[f * 4], hc[f][0], hc[f][1]);
        } else if (MODE == 3) {
            #pragma unroll
            for (int sh = 0; sh < 2; sh++) {
                uint32_t a[2][2][4];
                #pragma unroll
                for (int ss = 0; ss < 2; ss++) {
                    const int s = sh * 2 + ss;
                    #pragma unroll
                    for (int mf = 0; mf < 2; mf++) {
                        int row = wm0 + mf * 16 + (lane & 15);
                        uint32_t off = (uint32_t)(row * 128 + s * 32 + ((lane >> 4) << 4));
                        ldsm4(a[ss][mf][0], a[ss][mf][1], a[ss][mf][2], a[ss][mf][3],
                              ab + SW128(off));
                    }
                }
                #pragma unroll
                for (int cp = 0; cp < 4; cp++) {
                    uint32_t b[2][4];
                    #pragma unroll
                    for (int ss = 0; ss < 2; ss++) {
                        const int s = sh * 2 + ss;
                        int nrow = wn0 + cp * 16 + ((lane >> 4) << 3) + (lane & 7);
                        uint32_t off = (uint32_t)(nrow * 128 + s * 32 + (((lane >> 3) & 1) << 4));
                        ldsm4(b[ss][0], b[ss][1], b[ss][2], b[ss][3], bb + SW128(off));
                    }
                    #pragma unroll
                    for (int mf = 0; mf < 2; mf++) {
                        #pragma unroll
                        for (int nh = 0; nh < 2; nh++) {
                            uint32_t d0, d1;
                            mma_f16h0(d0, d1, a[0][mf][0], a[0][mf][1], a[0][mf][2], a[0][mf][3],
                                      b[0][nh * 2], b[0][nh * 2 + 1]);
                            mma_f16hc(d0, d1, a[1][mf][0], a[1][mf][1], a[1][mf][2], a[1][mf][3],
                                      b[1][nh * 2], b[1][nh * 2 + 1]);
                            hacc_add(&acc[(mf * 8 + cp * 2 + nh) * 4], d0, d1);
                        }
                    }
                }
            }
        } else {
            #pragma unroll
            for (int s = 0; s < 4; s++) {
                uint32_t a[2][4];
                #pragma unroll
                for (int mf = 0; mf < 2; mf++) {
                    int row = wm0 + mf * 16 + (lane & 15);
                    uint32_t off = (uint32_t)(row * 128 + s * 32 + ((lane >> 4) << 4));
                    ldsm4(a[mf][0], a[mf][1], a[mf][2], a[mf][3], ab + SW128(off));
                }
                #pragma unroll
                for (int cp = 0; cp < 4; cp++) {
                    uint32_t b0, b1, b2, b3;
                    int nrow = wn0 + cp * 16 + ((lane >> 4) << 3) + (lane & 7);
                    uint32_t off = (uint32_t)(nrow * 128 + s * 32 + (((lane >> 3) & 1) << 4));
                    ldsm4(b0, b1, b2, b3, bb + SW128(off));
                    #pragma unroll
                    for (int mf = 0; mf < 2; mf++) {
                        mma_f16(&acc[(mf * 8 + cp * 2 + 0) * 4],
                                a[mf][0], a[mf][1], a[mf][2], a[mf][3], b0, b1);
                        mma_f16(&acc[(mf * 8 + cp * 2 + 1) * 4],
                                a[mf][0], a[mf][1], a[mf][2], a[mf][3], b2, b3);
                    }
                }
            }
        }
        // no trailing barrier: the top-of-next-iteration barrier covers reuse
    }

    // Epilogue (MODE7 unpacks hm per-fragment)
    const int gid = lane >> 2, ctg = lane & 3;
    float*  Cf = (float*)Cout;
    __half* Ch = (__half*)Cout;
    #pragma unroll
    for (int mf = 0; mf < 2; mf++) {
        int r0 = m0 + wm0 + mf * 16 + gid;
        float s0 = 0.0f, s1 = 0.0f;
        if (act == 3) { s0 = sfa[r0]; s1 = sfa[r0 + 8]; }
        #pragma unroll
        for (int nf = 0; nf < 8; nf++) {
            float c[4];
            if (MODE == 7) {
                int f = mf * 8 + nf;
                float2 lo = __half22float2(*(__half2*)&hm[f][0]);
                float2 hi = __half22float2(*(__half2*)&hm[f][1]);
                c[0] = lo.x; c[1] = lo.y; c[2] = hi.x; c[3] = hi.y;
            } else {
                c[0] = acc[(mf * 8 + nf) * 4 + 0];
                c[1] = acc[(mf * 8 + nf) * 4 + 1];
                c[2] = acc[(mf * 8 + nf) * 4 + 2];
                c[3] = acc[(mf * 8 + nf) * 4 + 3];
            }
            int cc = n0 + wn0 + nf * 8 + ctg * 2;
            float2 bv2 = *(const float2*)(bias + cc);
            float v0 = c[0], v1 = c[1], v2 = c[2], v3 = c[3];
            if (act == 3) {
                float2 x0 = *(const float2*)(xadd + (size_t)r0 * ldc + cc);
                float2 x1 = *(const float2*)(xadd + (size_t)(r0 + 8) * ldc + cc);
                v0 += x0.x + s0 * bv2.x; v1 += x0.y + s0 * bv2.y;
                v2 += x1.x + s1 * bv2.x; v3 += x1.y + s1 * bv2.y;
            } else {
                v0 += bv2.x; v1 += bv2.y; v2 += bv2.x; v3 += bv2.y;
                if (act == 1) {
                    v0 = gelu_exact(v0); v1 = gelu_exact(v1);
                    v2 = gelu_exact(v2); v3 = gelu_exact(v3);
                }
            }
            if (out_half) {
                *(__half2*)(Ch + (size_t)r0 * ldc + cc)       = __floats2half2_rn(v0, v1);
                *(__half2*)(Ch + (size_t)(r0 + 8) * ldc + cc) = __floats2half2_rn(v2, v3);
            } else {
                float2 o0 = {v0, v1}, o1 = {v2, v3};
                *(float2*)(Cf + (size_t)r0 * ldc + cc) = o0;
                *(float2*)(Cf + (size_t)(r0 + 8) * ldc + cc) = o1;
            }
        }
    }
}

// ----------------------------------------------------------------------------
// Merged prepass: transposes, weight f2h, bias precomputes — one launch.
// ----------------------------------------------------------------------------
__global__ void prep_all(
    __half* __restrict__ Wqt, const float* __restrict__ Wq,
    __half* __restrict__ Wkt, const float* __restrict__ Wk,
    __half* __restrict__ Wvh, const float* __restrict__ Wv,
    __half* __restrict__ Wuph, const float* __restrict__ Wup,
    __half* __restrict__ Wdnh, const float* __restrict__ Wdown,
    float* __restrict__ vqk, float* __restrict__ vkq,
    const float* __restrict__ bq, const float* __restrict__ bk,
    float* __restrict__ pqbv, float* __restrict__ c0,
    const float* __restrict__ pq, const float* __restrict__ bv,
    float* __restrict__ PV)
{
    __shared__ float tile[32][33];
    const int b   = blockIdx.x;
    const int tx  = threadIdx.x, ty = threadIdx.y;
    const int tid = ty * 32 + tx;

    if (b < 2048) {
        int z = b >> 10, r = b & 1023;
        const float* src = z ? Wk : Wq;
        __half* dst = z ? Wkt : Wqt;
        int bx = (r & 31) * 32, by = (r >> 5) * 32;
        #pragma unroll
        for (int rr = 0; rr < 32; rr += 8)
            tile[ty + rr][tx] = src[(size_t)(by + ty + rr) * Dd + bx + tx];
        __syncthreads();
        #pragma unroll
        for (int rr = 0; rr < 32; rr += 8)
            dst[(size_t)(bx + ty + rr) * Dd + by + tx] = __float2half_rn(tile[tx][ty + rr]);
    } else if (b < 3072) {
        int i = (b - 2048) * 256 + tid;
        float4 v = ((const float4*)Wv)[i];
        ((__half2*)Wvh)[2 * i]     = __floats2half2_rn(v.x, v.y);
        ((__half2*)Wvh)[2 * i + 1] = __floats2half2_rn(v.z, v.w);
    } else if (b < 7168) {
        int i = (b - 3072) * 256 + tid;
        float4 v = ((const float4*)Wup)[i];
        ((__half2*)Wuph)[2 * i]     = __floats2half2_rn(v.x, v.y);
        ((__half2*)Wuph)[2 * i + 1] = __floats2half2_rn(v.z, v.w);
    } else if (b < 11264) {
        int i = (b - 7168) * 256 + tid;
        float4 v = ((const float4*)Wdown)[i];
        ((__half2*)Wdnh)[2 * i]     = __floats2half2_rn(v.x, v.y);
        ((__half2*)Wdnh)[2 * i + 1] = __floats2half2_rn(v.z, v.w);
    } else if (b < 11272) {
        int idx = (b - 11264) * 256 + tid;
        if (idx < Dd) {
            float a = 0.0f;
            for (int e = 0; e < Dd; e++) a = fmaf(Wq[(size_t)e * Dd + idx], bk[e], a);
            vqk[idx] = a;
        } else {
            int d = idx - Dd;
            float a = 0.0f;
            for (int e = 0; e < Dd; e++) a = fmaf(Wk[(size_t)e * Dd + d], bq[e], a);
            vkq[d] = a;
        }
    } else if (b < 11305) {
        __shared__ float red[256];
        int bb = b - 11272;
        float a = 0.0f;
        if (bb < 32) {
            for (int e = tid; e < Dd; e += 256) a = fmaf(pq[(size_t)bb * Dd + e], bv[e], a);
        } else {
            for (int e = tid; e < Dd; e += 256) a = fmaf(bq[e], bk[e], a);
        }
        red[tid] = a; __syncthreads();
        for (int o = 128; o > 0; o >>= 1) { if (tid < o) red[tid] += red[tid + o]; __syncthreads(); }
        if (tid == 0) { if (bb < 32) pqbv[bb] = red[0]; else c0[0] = red[0]; }
    } else {
        int idx = b - 11305;
        int p = idx >> 2;
        int d = (idx & 3) * 256 + tid;
        float a = 0.0f;
        for (int e = 0; e < Dd; e++) a = fmaf(pq[(size_t)p * Dd + e], Wv[(size_t)e * Dd + d], a);
        PV[(size_t)p * Dd + d] = a;
    }
}

__global__ void f2h_k(__half* __restrict__ d, const float* __restrict__ s, int n4) {
    int i = blockIdx.x * blockDim.x + threadIdx.x;
    if (i < n4) {
        float4 v = ((const float4*)s)[i];
        ((__half2*)d)[2 * i]     = __floats2half2_rn(v.x, v.y);
        ((__half2*)d)[2 * i + 1] = __floats2half2_rn(v.z, v.w);
    }
}

// ----------------------------------------------------------------------------
// Fused per-token attention (factored). Reads U + sn (fp16); emits agg_mix(fp16)+sfa.
// ----------------------------------------------------------------------------
#define ATTN_SMEM ((8 * 1028 * 2 + 1028 + 1024) * 4)

__global__ __launch_bounds__(256, 2) void attn_fused(
    const __half* __restrict__ U, const __half* __restrict__ sn,
    const float* __restrict__ pq, const float* __restrict__ PV,
    const float* __restrict__ ctx, const float* __restrict__ tw,
    const float* __restrict__ vqk, const float* __restrict__ vkq,
    const float* __restrict__ pqbv, const float* __restrict__ c0p,
    __half* __restrict__ aggmix, float* __restrict__ sfaout)
{
    extern __shared__ float dynsm[];
    float* sSn   = dynsm;
    float* sMix  = sSn + 8 * 1028;
    float* sWMix = sMix + 8 * 1028;
    float* sCtx  = sWMix + 1028;

    __shared__ float sA[8][8];
    __shared__ float sW[8], sTq[8], sTk[8];
    __shared__ float sNB[32], sCB[32];
    __shared__ float sSel[4][8];
    __shared__ float sTw[4];
    __shared__ int   sTi[4];
    __shared__ float sFA[8];
    __shared__ float sC0;

    const int tok  = blockIdx.x;
    const int t    = threadIdx.x;
    const int warp = t >> 5;
    const int lane = t & 31;
    const float scale = 0.03125f;

    const __half* snt = sn + (size_t)tok * 8 * 1024;
    const __half* Ut  = U + (size_t)tok * 8 * 1024;

    if (t < 8) sW[t] = tw[tok * 8 + t];
    if (t == 0) sC0 = c0p[0];
    #pragma unroll
    for (int r = 0; r < 16; r++) {
        int i2 = t + 256 * r;
        __half2 v = ((const __half2*)snt)[i2];
        int d = i2 * 2;
        float* row = sSn + (d >> 10) * 1028 + (d & 1023);
        row[0] = __half2float(v.x); row[1] = __half2float(v.y);
    }
    #pragma unroll
    for (int r = 0; r < 4; r++) sCtx[t + 256 * r] = ctx[(size_t)tok * 1024 + t + 256 * r];
    __syncthreads();

    // ---- Stage 1 ----
    float sc[8] = {0, 0, 0, 0, 0, 0, 0, 0};
    {
        const int i = warp;
        const __half2* Urow = (const __half2*)(Ut + i * 1024);
        float tq = 0.0f, tk = 0.0f;
        for (int c = 0; c < 4; c++) {
            float2 uc[4];
            #pragma unroll
            for (int u = 0; u < 4; u++)
                uc[u] = __half22float2(Urow[c * 128 + u * 32 + lane]);
            #pragma unroll
            for (int j = 0; j < 8; j++) {
                const float* sj = sSn + j * 1028 + c * 256;
                float a = 0.0f;
                #pragma unroll
                for (int u = 0; u < 4; u++) {
                    float2 sv = *(const float2*)(sj + u * 64 + 2 * lane);
                    a = fmaf(uc[u].x, sv.x, a);
                    a = fmaf(uc[u].y, sv.y, a);
                }
                sc[j] += a;
            }
            const float* si = sSn + i * 1028 + c * 256;
            #pragma unroll
            for (int u = 0; u < 4; u++) {
                float2 sv = *(const float2*)(si + u * 64 + 2 * lane);
                float2 vq = *(const float2*)(vqk + c * 256 + u * 64 + 2 * lane);
                float2 vk = *(const float2*)(vkq + c * 256 + u * 64 + 2 * lane);
                tq = fmaf(sv.x, vq.x, tq); tq = fmaf(sv.y, vq.y, tq);
                tk = fmaf(sv.x, vk.x, tk); tk = fmaf(sv.y, vk.y, tk);
            }
        }
        #pragma unroll
        for (int j = 0; j < 8; j++) {
            float a = sc[j];
            #pragma unroll
            for (int o = 16; o > 0; o >>= 1) a += __shfl_xor_sync(0xffffffffu, a, o);
            sc[j] = a;
        }
        #pragma unroll
        for (int o = 16; o > 0; o >>= 1) {
            tq += __shfl_xor_sync(0xffffffffu, tq, o);
            tk += __shfl_xor_sync(0xffffffffu, tk, o);
        }
        if (lane == 0) { sTq[i] = tq; sTk[i] = tk; }
    }
    __syncthreads();
    {
        const int i = warp;
        float tqi = sTq[i], c0v = sC0;
        float f[8];
        #pragma unroll
        for (int j = 0; j < 8; j++) f[j] = (sc[j] + tqi + sTk[j] + c0v) * scale;
        if (lane == 0) {
            float m = f[0];
            #pragma unroll
            for (int j = 1; j < 8; j++) m = fmaxf(m, f[j]);
            float e[8], s = 0.0f;
            #pragma unroll
            for (int j = 0; j < 8; j++) { e[j] = expf(f[j] - m); s += e[j]; }
            float inv = 1.0f / s;
            #pragma unroll
            for (int j = 0; j < 8; j++) sA[i][j] = e[j] * inv;
        }
    }
    __syncthreads();

    // ---- Stage 2 ----
    #pragma unroll
    for (int r = 0; r < 4; r++) {
        int d = t + 256 * r;
        float a[8] = {0,0,0,0,0,0,0,0};
        #pragma unroll
        for (int j = 0; j < 8; j++) {
            float s = sSn[j * 1028 + d];
            #pragma unroll
            for (int i = 0; i < 8; i++) a[i] = fmaf(sA[i][j], s, a[i]);
        }
        float wm = 0.0f;
        #pragma unroll
        for (int i = 0; i < 8; i++) { sMix[i * 1028 + d] = a[i]; wm = fmaf(sW[i], a[i], wm); }
        sWMix[d] = wm;
    }
    __syncthreads();

    // ---- Stage 3 ----
    float swsum = sW[0] + sW[1] + sW[2] + sW[3] + sW[4] + sW[5] + sW[6] + sW[7];
    #pragma unroll
    for (int q = 0; q < 4; q++) {
        int p = warp * 4 + q;
        const float* PVp = PV + (size_t)p * 1024;
        const float* pqp = pq + (size_t)p * 1024;
        float nb = 0.0f, cb = 0.0f;
        #pragma unroll
        for (int u = 0; u < 32; u++) {
            int d = u * 32 + lane;
            nb = fmaf(PVp[d], sWMix[d], nb);
            cb = fmaf(pqp[d], sCtx[d], cb);
        }
        #pragma unroll
        for (int o = 16; o > 0; o >>= 1) {
            nb += __shfl_xor_sync(0xffffffffu, nb, o);
            cb += __shfl_xor_sync(0xffffffffu, cb, o);
        }
        if (lane == 0) { sNB[p] = (nb + swsum * pqbv[p]) * scale; sCB[p] = cb; }
    }
    __syncthreads();

    // ---- Stage 4 ----
    if (warp == 0) {
        float s = 0.5f * sNB[lane] + 0.5f * sCB[lane];
        float vals[4]; int ids[4];
        #pragma unroll
        for (int r = 0; r < 4; r++) {
            float v = s; int idx = lane;
            #pragma unroll
            for (int o = 16; o > 0; o >>= 1) {
                float ov = __shfl_xor_sync(0xffffffffu, v, o);
                int   oi = __shfl_xor_sync(0xffffffffu, idx, o);
                if (ov > v || (ov == v && oi < idx)) { v = ov; idx = oi; }
            }
            vals[r] = v; ids[r] = idx;
            if (lane == idx) s = -3.4e38f;
        }
        if (lane == 0) {
            float m = fmaxf(fmaxf(vals[0], vals[1]), fmaxf(vals[2], vals[3]));
            float e0 = expf(vals[0] - m), e1 = expf(vals[1] - m);
            float e2 = expf(vals[2] - m), e3 = expf(vals[3] - m);
            float inv = 1.0f / (e0 + e1 + e2 + e3);
            sTw[0] = e0 * inv; sTw[1] = e1 * inv; sTw[2] = e2 * inv; sTw[3] = e3 * inv;
            sTi[0] = ids[0]; sTi[1] = ids[1]; sTi[2] = ids[2]; sTi[3] = ids[3];
        }
    }
    __syncthreads();

    // ---- Stage 5 ----
    if (warp < 4) {
        int pi = sTi[warp];
        const float* PVp = PV + (size_t)pi * 1024;
        float pvr[32];
        #pragma unroll
        for (int u = 0; u < 32; u++) pvr[u] = PVp[u * 32 + lane];
        float sel[8];
        #pragma unroll
        for (int k = 0; k < 8; k++) {
            float a = 0.0f;
            #pragma unroll
            for (int u = 0; u < 32; u++)
                a = fmaf(pvr[u], sMix[k * 1028 + u * 32 + lane], a);
            #pragma unroll
            for (int o = 16; o > 0; o >>= 1) a += __shfl_xor_sync(0xffffffffu, a, o);
            sel[k] = a;
        }
        if (lane == 0) {
            float pb = pqbv[pi];
            #pragma unroll
            for (int k = 0; k < 8; k++) sel[k] = (sel[k] + pb) * scale;
            float m = sel[0];
            #pragma unroll
            for (int k = 1; k < 8; k++) m = fmaxf(m, sel[k]);
            float e[8], sum = 0.0f;
            #pragma unroll
            for (int k = 0; k < 8; k++) { e[k] = expf(sel[k] - m); sum += e[k]; }
            float f = sTw[warp] / sum;
            #pragma unroll
            for (int k = 0; k < 8; k++) sSel[warp][k] = e[k] * f;
        }
    }
    __syncthreads();
    if (t < 8) sFA[t] = sSel[0][t] + sSel[1][t] + sSel[2][t] + sSel[3][t];
    __syncthreads();

    // ---- Stage 6 ----
    float fa[8];
    #pragma unroll
    for (int k = 0; k < 8; k++) fa[k] = sFA[k];
    if (t == 0)
        sfaout[tok] = fa[0] + fa[1] + fa[2] + fa[3] + fa[4] + fa[5] + fa[6] + fa[7];
    #pragma unroll
    for (int r = 0; r < 4; r++) {
        int d = t + 256 * r;
        float a = 0.0f;
        #pragma unroll
        for (int k = 0; k < 8; k++) a = fmaf(fa[k], sMix[k * 1028 + d], a);
        aggmix[(size_t)tok * 1024 + d] = __float2half_rn(a);
    }
}

// ----------------------------------------------------------------------------
// Launch (U GEMM is launch #4 = ncu profile target)
// ----------------------------------------------------------------------------
extern "C" void kernel_launch(void* const* d_in, const int* in_sizes, int n_in,
                              void* d_out, int out_size)
{
    const float* x     = (const float*)d_in[0];
    const float* tw    = (const float*)d_in[3];
    const float* sn    = (const float*)d_in[4];
    const float* ctx   = (const float*)d_in[5];
    const float* Wq    = (const float*)d_in[6];
    const float* bq    = (const float*)d_in[7];
    const float* Wk    = (const float*)d_in[8];
    const float* bk    = (const float*)d_in[9];
    const float* Wv    = (const float*)d_in[10];
    const float* bv    = (const float*)d_in[11];
    const float* pq    = (const float*)d_in[12];
    const float* Wup   = (const float*)d_in[13];
    const float* bup   = (const float*)d_in[14];
    const float* Wdown = (const float*)d_in[15];
    const float* bdown = (const float*)d_in[16];
    float* out = (float*)d_out;

    __half *snh, *Up, *comb, *h, *aggmix, *Wqt, *Wkt, *Mt, *Wvh, *Wuph, *Wdnh;
    float *sfa, *PV, *vqk, *vkq, *pqbv, *c0, *zeros;
    cudaGetSymbolAddress((void**)&snh,    g_sn_h);
    cudaGetSymbolAddress((void**)&Up,     g_U);
    cudaGetSymbolAddress((void**)&comb,   g_comb);
    cudaGetSymbolAddress((void**)&h,      g_h);
    cudaGetSymbolAddress((void**)&aggmix, g_aggmix);
    cudaGetSymbolAddress((void**)&sfa,    g_sfa);
    cudaGetSymbolAddress((void**)&Wqt,    g_Wqt);
    cudaGetSymbolAddress((void**)&Wkt,    g_Wkt);
    cudaGetSymbolAddress((void**)&Mt,     g_Mt);
    cudaGetSymbolAddress((void**)&Wvh,    g_Wvh);
    cudaGetSymbolAddress((void**)&Wuph,   g_Wuph);
    cudaGetSymbolAddress((void**)&Wdnh,   g_Wdnh);
    cudaGetSymbolAddress((void**)&PV,     g_PV);
    cudaGetSymbolAddress((void**)&vqk,    g_vqk);
    cudaGetSymbolAddress((void**)&vkq,    g_vkq);
    cudaGetSymbolAddress((void**)&pqbv,   g_pqbv);
    cudaGetSymbolAddress((void**)&c0,     g_c0);
    cudaGetSymbolAddress((void**)&zeros,  g_zeros);

    cudaFuncSetAttribute((const void*)gemm_h<0>, cudaFuncAttributeMaxDynamicSharedMemorySize, DYN_SMEM);
    cudaFuncSetAttribute((const void*)gemm_h<3>, cudaFuncAttributeMaxDynamicSharedMemorySize, DYN_SMEM);
    cudaFuncSetAttribute((const void*)gemm_h<7>, cudaFuncAttributeMaxDynamicSharedMemorySize, DYN_SMEM);
    cudaFuncSetAttribute((const void*)gemm_h<8>, cudaFuncAttributeMaxDynamicSharedMemorySize, DYN_SMEM);
    cudaFuncSetAttribute(attn_fused, cudaFuncAttributeMaxDynamicSharedMemorySize, ATTN_SMEM);

    // #1: merged prepass (transposes + weight f2h + bias precomputes)
    prep_all<<<11433, dim3(32, 8)>>>(Wqt, Wq, Wkt, Wk, Wvh, Wv, Wuph, Wup,
                                     Wdnh, Wdown, vqk, vkq, bq, bk,
                                     pqbv, c0, pq, bv, PV);
    // #2: sn -> fp16
    int n4 = (MQKV * Dd) / 4;
    f2h_k<<<(n4 + 255) / 256, 256>>>(snh, sn, n4);
    // #3: Mt = Wkt @ Wqt^T (f32 accum, small)
    gemm_h<0><<<64, 256, DYN_SMEM>>>(Wkt, Dd, Wqt, zeros, Mt, Dd,
                                     Dd, 8, 8, 0, 1, nullptr, nullptr);
    // #4: U = sn_h @ Mt^T -> fp16  [MODE7, single-barrier mainloop] (PROFILE)
    gemm_h<7><<<2048, 256, DYN_SMEM>>>(snh, Dd, Mt, zeros, Up, Dd,
                                       Dd, 8, 8, 0, 1, nullptr, nullptr);

    // fused attention -> agg_mix (fp16), sfa
    attn_fused<<<NTOK, 256, ATTN_SMEM>>>(Up, snh, pq, PV, ctx, tw,
                                         vqk, vkq, pqbv, c0, aggmix, sfa);

    // comb = x + agg_mix @ Wv^T + sfa*bv  [MODE7]
    gemm_h<7><<<256, 256, DYN_SMEM>>>(aggmix, Dd, Wvh, bv, comb, Dd,
                                      Dd, 8, 16, 3, 1, x, sfa);

    // FFN up (+GELU)  [MODE8]
    gemm_h<8><<<1024, 256, DYN_SMEM>>>(comb, Dd, Wuph, bup, h, DFFd,
                                       Dd, 32, 8, 1, 1, nullptr, nullptr);

    // FFN down -> fp32 output  [MODE3]
    gemm_h<3><<<256, 256, DYN_SMEM>>>(h, DFFd, Wdnh, bdown, out, Dd,
                                      DFFd, 8, 16, 0, 0, nullptr, nullptr);
}